// round 4
// baseline (speedup 1.0000x reference)
#include <cuda_runtime.h>
#include <math.h>

#define BB 4
#define CC 64
#define OO 64
#define HH 128
#define WW 128
#define HW (HH*WW)
#define KT 9

// ---- smem layout (float offsets) ----
#define S_SAMP0 0        // [64][128]
#define S_SAMP1 8192     // [64][128]
#define S_W     16384    // [64][64]
#define S_OFFJ  20480    // [18][128]
#define S_OFFW  22784    // [64][20]
#define S_SC    24064
#define S_SB    24082
#define S_BIAS  24100
#define SMEM_FLOATS 24164
#define SMEM_BYTES (SMEM_FLOATS*4)

// transposed weights [k][c][o]
__device__ float g_wt[KT*CC*OO];

__global__ void prep_wt_kernel(const float* __restrict__ w) {
    int i = blockIdx.x * 256 + threadIdx.x;
    if (i >= KT*CC*OO) return;
    int o = i % OO;
    int c = (i / OO) % CC;
    int k = i / (OO*CC);
    g_wt[i] = w[(o*CC + c)*KT + k];
}

__device__ __forceinline__ unsigned long long dup2(float a) {
    unsigned long long r;
    asm("mov.b64 %0, {%1, %1};" : "=l"(r) : "f"(a));
    return r;
}
__device__ __forceinline__ void fma2(unsigned long long& d, unsigned long long a, unsigned long long b) {
    asm("fma.rn.f32x2 %0, %1, %2, %0;" : "+l"(d) : "l"(a), "l"(b));
}
__device__ __forceinline__ void unpack2(unsigned long long v, float& lo, float& hi) {
    asm("mov.b64 {%0, %1}, %2;" : "=f"(lo), "=f"(hi) : "l"(v));
}

__global__ __launch_bounds__(256, 2) void deform_main_kernel(
    const float* __restrict__ x,
    const float* __restrict__ off_w,
    const float* __restrict__ off_b,
    const float* __restrict__ bn_gamma,
    const float* __restrict__ bn_beta,
    const float* __restrict__ bn_mean,
    const float* __restrict__ bn_var,
    const float* __restrict__ dconv_b,
    float* __restrict__ out)
{
    extern __shared__ float smem[];

    const int tid  = threadIdx.x;
    const int lane = tid & 31;
    const int wrp  = tid >> 5;
    const int b    = blockIdx.x >> 7;
    const int h    = blockIdx.x & 127;
    const int pix  = tid & 127;       // gather pixel
    const int half = tid >> 7;        // 0/1: c-parity this thread gathers
    const float* xb = x + (size_t)b * CC * HW;

    // contraction tile: 8 pixels x 4 o per thread
    // warp = 8 o-groups x 4 pixel-groups
    const int o_base   = ((lane & 7) + ((wrp & 1) << 3)) * 4;   // 16 groups of 4
    const int pix_base = ((lane >> 3) + ((wrp >> 1) << 2)) * 8; // 16 groups of 8

    // ---- Prologue ----
    for (int i = tid; i < 18*CC; i += 256) {
        int j = i / CC, c = i % CC;
        smem[S_OFFW + c*20 + j] = off_w[i];
    }
    if (tid < 18) {
        float sc = bn_gamma[tid] * rsqrtf(bn_var[tid] + 1e-5f);
        smem[S_SC + tid] = sc;
        smem[S_SB + tid] = (off_b[tid] - bn_mean[tid]) * sc + bn_beta[tid];
    }
    if (tid < OO) smem[S_BIAS + tid] = dconv_b[tid];
    __syncthreads();

    // ---- Offset branch: 2 threads per pixel, 9 j's each ----
    {
        const int jb = half * 9;
        const int p  = h*WW + pix;
        float a9[9];
        #pragma unroll
        for (int j = 0; j < 9; j++) a9[j] = 0.f;
        #pragma unroll 4
        for (int c = 0; c < CC; c++) {
            float xv = __ldg(xb + c*HW + p);
            const float* r = smem + S_OFFW + c*20 + jb;
            #pragma unroll
            for (int j = 0; j < 9; j++) a9[j] += xv * r[j];
        }
        #pragma unroll
        for (int jj = 0; jj < 9; jj++) {
            int j = jb + jj;
            float v = a9[jj] * smem[S_SC + j] + smem[S_SB + j];
            smem[S_OFFJ + j*128 + pix] = tanhf(v) * 0.75f;
        }
    }
    __syncthreads();

    // corner computation for tap k at this thread's gather pixel
    auto corners = [&](int k, float4& wv, int4& iv) {
        const int kyi = k / 3 - 1;
        const int kxi = k % 3 - 1;
        float py = (float)(h + kyi)   + smem[S_OFFJ + (2*k)*128 + pix];
        float px = (float)(pix + kxi) + smem[S_OFFJ + (2*k+1)*128 + pix];
        float fy = floorf(py), fx = floorf(px);
        float wy = py - fy,    wx = px - fx;
        int y0 = (int)fy, x0 = (int)fx;
        int y1 = y0 + 1,  x1 = x0 + 1;
        float vy0 = (y0 >= 0 && y0 < HH) ? 1.f : 0.f;
        float vy1 = (y1 >= 0 && y1 < HH) ? 1.f : 0.f;
        float vx0 = (x0 >= 0 && x0 < WW) ? 1.f : 0.f;
        float vx1 = (x1 >= 0 && x1 < WW) ? 1.f : 0.f;
        wv.x = (1.f - wy) * (1.f - wx) * vy0 * vx0;
        wv.y = (1.f - wy) * wx         * vy0 * vx1;
        wv.z = wy         * (1.f - wx) * vy1 * vx0;
        wv.w = wy         * wx         * vy1 * vx1;
        int yc0 = min(max(y0, 0), HH-1), yc1 = min(max(y1, 0), HH-1);
        int xc0 = min(max(x0, 0), WW-1), xc1 = min(max(x1, 0), WW-1);
        iv.x = yc0*WW + xc0; iv.y = yc0*WW + xc1;
        iv.z = yc1*WW + xc0; iv.w = yc1*WW + xc1;
    };

    // ---- Pre-loop: gather tap 0 -> SAMP0, stage weights tap 0 -> S_W ----
    {
        float4 wv; int4 iv;
        corners(0, wv, iv);
        const float4* wsrc = (const float4*)g_wt;
        float4* wdst = (float4*)(smem + S_W);
        #pragma unroll
        for (int q = 0; q < 4; q++) wdst[tid + 256*q] = wsrc[tid + 256*q];
        #pragma unroll 4
        for (int i = 0; i < 32; i++) {
            int c = half + 2*i;
            const float* bp = xb + c*HW;
            float v00 = __ldg(bp + iv.x), v01 = __ldg(bp + iv.y);
            float v10 = __ldg(bp + iv.z), v11 = __ldg(bp + iv.w);
            smem[S_SAMP0 + c*128 + pix] = wv.x*v00 + wv.y*v01 + wv.z*v10 + wv.w*v11;
        }
    }
    __syncthreads();

    // ---- Main pipelined loop ----
    // accp[pp*4 + j]: pixel pair pp (pix_base+2pp, +2pp+1), output o_base+j
    unsigned long long accp[16];
    #pragma unroll
    for (int i = 0; i < 16; i++) accp[i] = 0ULL;

    #pragma unroll 1
    for (int k = 0; k < KT; k++) {
        const float* s_cur = smem + ((k & 1) ? S_SAMP1 : S_SAMP0);
        float*       s_nxt = smem + ((k & 1) ? S_SAMP0 : S_SAMP1);
        const bool pf = (k < KT-1);

        float4 wv; int4 iv;
        float4 wst[4];
        if (pf) {
            corners(k+1, wv, iv);
            const float4* wsrc = (const float4*)(g_wt + (k+1)*CC*OO);
            #pragma unroll
            for (int q = 0; q < 4; q++) wst[q] = __ldg(wsrc + tid + 256*q);
        }

        const float* samp_base = s_cur + pix_base;
        const float* w_base    = smem + S_W + o_base;

        #pragma unroll
        for (int cc = 0; cc < 8; cc++) {
            float v[16];
            if (pf) {
                #pragma unroll
                for (int e = 0; e < 4; e++) {
                    int c = half + 2*(cc*4 + e);
                    const float* bp = xb + c*HW;
                    v[4*e+0] = __ldg(bp + iv.x);
                    v[4*e+1] = __ldg(bp + iv.y);
                    v[4*e+2] = __ldg(bp + iv.z);
                    v[4*e+3] = __ldg(bp + iv.w);
                }
            }
            #pragma unroll
            for (int u = 0; u < 8; u++) {
                int c = cc*8 + u;
                // samp pairs load directly as f32x2 operands
                ulonglong2 sa = *(const ulonglong2*)(samp_base + c*128);      // pix 0..3
                ulonglong2 sb = *(const ulonglong2*)(samp_base + c*128 + 4);  // pix 4..7
                float4 wf = *(const float4*)(w_base + c*64);
                unsigned long long w0 = dup2(wf.x);
                unsigned long long w1 = dup2(wf.y);
                unsigned long long w2 = dup2(wf.z);
                unsigned long long w3 = dup2(wf.w);
                fma2(accp[ 0], sa.x, w0); fma2(accp[ 1], sa.x, w1);
                fma2(accp[ 2], sa.x, w2); fma2(accp[ 3], sa.x, w3);
                fma2(accp[ 4], sa.y, w0); fma2(accp[ 5], sa.y, w1);
                fma2(accp[ 6], sa.y, w2); fma2(accp[ 7], sa.y, w3);
                fma2(accp[ 8], sb.x, w0); fma2(accp[ 9], sb.x, w1);
                fma2(accp[10], sb.x, w2); fma2(accp[11], sb.x, w3);
                fma2(accp[12], sb.y, w0); fma2(accp[13], sb.y, w1);
                fma2(accp[14], sb.y, w2); fma2(accp[15], sb.y, w3);
            }
            if (pf) {
                #pragma unroll
                for (int e = 0; e < 4; e++) {
                    int c = half + 2*(cc*4 + e);
                    s_nxt[c*128 + pix] =
                        wv.x*v[4*e+0] + wv.y*v[4*e+1] + wv.z*v[4*e+2] + wv.w*v[4*e+3];
                }
            }
        }

        __syncthreads();   // next samp complete; weights consumed
        if (pf) {
            float4* wdst = (float4*)(smem + S_W);
            #pragma unroll
            for (int q = 0; q < 4; q++) wdst[tid + 256*q] = wst[q];
            __syncthreads();
        }
    }

    // ---- Epilogue: per o, 8 pixels = 2 float4 stores ----
    const int pb = h*WW + pix_base;
    #pragma unroll
    for (int j = 0; j < 4; j++) {
        int o = o_base + j;
        float bias = smem[S_BIAS + o];
        float lo0, hi0, lo1, hi1, lo2, hi2, lo3, hi3;
        unpack2(accp[0*4 + j], lo0, hi0);
        unpack2(accp[1*4 + j], lo1, hi1);
        unpack2(accp[2*4 + j], lo2, hi2);
        unpack2(accp[3*4 + j], lo3, hi3);
        float4 v0 = make_float4(lo0+bias, hi0+bias, lo1+bias, hi1+bias);
        float4 v1 = make_float4(lo2+bias, hi2+bias, lo3+bias, hi3+bias);
        float* op = out + ((size_t)(b*OO + o))*HW + pb;
        *(float4*)op       = v0;
        *(float4*)(op + 4) = v1;
    }
}

extern "C" void kernel_launch(void* const* d_in, const int* in_sizes, int n_in,
                              void* d_out, int out_size) {
    const float* x        = (const float*)d_in[0];
    const float* off_w    = (const float*)d_in[1];
    const float* off_b    = (const float*)d_in[2];
    const float* bn_gamma = (const float*)d_in[3];
    const float* bn_beta  = (const float*)d_in[4];
    const float* bn_mean  = (const float*)d_in[5];
    const float* bn_var   = (const float*)d_in[6];
    const float* dconv_w  = (const float*)d_in[7];
    const float* dconv_b  = (const float*)d_in[8];
    float* out = (float*)d_out;

    cudaFuncSetAttribute(deform_main_kernel,
                         cudaFuncAttributeMaxDynamicSharedMemorySize, SMEM_BYTES);

    prep_wt_kernel<<<(KT*CC*OO + 255)/256, 256>>>(dconv_w);
    deform_main_kernel<<<BB*HH, 256, SMEM_BYTES>>>(
        x, off_w, off_b, bn_gamma, bn_beta, bn_mean, bn_var, dconv_b, out);
}